// round 1
// baseline (speedup 1.0000x reference)
#include <cuda_runtime.h>
#include <math.h>

#define BB   8
#define NN   1024
#define FF   128
#define HH   8
#define MAXN 256
#define PRED_IN 384
#define LDIM 2

// ---------------- device scratch (module globals: allowed) ----------------
__device__ int   g_nbr[BB * NN * MAXN];          // 8 MB
__device__ int   g_cnt[BB * NN];
__device__ float g_hp[BB * HH * NN * FF];        // 32 MB
__device__ float g_s[BB * HH * NN];
__device__ float g_d[BB * HH * NN];
__device__ float g_x1[BB * NN * FF];             // 4 MB each
__device__ float g_x2[BB * NN * FF];
__device__ float g_x3[BB * NN * FF];
__device__ float g_pmax[BB * 8 * PRED_IN];

// ---------------- K1: adjacency -> neighbor lists (warp per row) -----------
__global__ __launch_bounds__(256) void build_nbr(const float* __restrict__ adj) {
    int wgl  = blockIdx.x * 8 + (threadIdx.x >> 5);   // global warp id = row id
    int lane = threadIdx.x & 31;
    int b = wgl / NN;
    int i = wgl % NN;
    const float* row = adj + (size_t)(b * NN + i) * NN;
    int base = 0;
    for (int c = 0; c < NN; c += 32) {
        float v = row[c + lane];
        unsigned m = __ballot_sync(0xffffffffu, v > 0.0f);
        if (v > 0.0f) {
            int pos = base + __popc(m & ((1u << lane) - 1u));
            if (pos < MAXN) g_nbr[(b * NN + i) * MAXN + pos] = c + lane;
        }
        base += __popc(m);
    }
    if (lane == 0) g_cnt[b * NN + i] = min(base, MAXN);
}

// ---------------- K2: hp = x @ w[h], fused tanh-dot epilogue (s,d) ---------
// grid (N/64, H, B), 256 threads. Tile: 64 rows x 128 cols, thread = 4x8.
__global__ __launch_bounds__(256) void gat_gemm(const float* __restrict__ x,
                                                const float* __restrict__ w,
                                                const float* __restrict__ asrc,
                                                const float* __restrict__ adst) {
    const int rb = blockIdx.x;
    const int h  = blockIdx.y;
    const int b  = blockIdx.z;

    __shared__ float As[16][65];      // k-major, padded
    __shared__ float Bs[16][128];
    __shared__ float sa[FF], da[FF];
    __shared__ float redA[64][16];
    __shared__ float redB[64][16];

    const int tid = threadIdx.x;
    const int ty = tid >> 4;          // 0..15  (row group, 4 rows each)
    const int tx = tid & 15;          // 0..15  (col group, 8 cols each)

    if (tid < FF) { sa[tid] = asrc[h * FF + tid]; da[tid] = adst[h * FF + tid]; }

    const float* xb = x + (size_t)(b * NN + rb * 64) * FF;
    const float* wh = w + (size_t)h * FF * FF;

    float acc[4][8];
#pragma unroll
    for (int r = 0; r < 4; r++)
#pragma unroll
        for (int c = 0; c < 8; c++) acc[r][c] = 0.0f;

    const int lk = tid & 15, ln = tid >> 4;     // A-tile load mapping
    const int bo = (tid & 31) * 4, bk = tid >> 5; // B-tile load mapping (float4)

    for (int k0 = 0; k0 < FF; k0 += 16) {
#pragma unroll
        for (int t = 0; t < 4; t++)
            As[lk][ln + 16 * t] = xb[(ln + 16 * t) * FF + k0 + lk];
#pragma unroll
        for (int t = 0; t < 2; t++)
            *(float4*)&Bs[bk + 8 * t][bo] =
                *(const float4*)&wh[(size_t)(k0 + bk + 8 * t) * FF + bo];
        __syncthreads();
#pragma unroll
        for (int kk = 0; kk < 16; kk++) {
            float av[4], bv[8];
#pragma unroll
            for (int r = 0; r < 4; r++) av[r] = As[kk][ty * 4 + r];
            float4 b0 = *(const float4*)&Bs[kk][tx * 8];
            float4 b1 = *(const float4*)&Bs[kk][tx * 8 + 4];
            bv[0]=b0.x; bv[1]=b0.y; bv[2]=b0.z; bv[3]=b0.w;
            bv[4]=b1.x; bv[5]=b1.y; bv[6]=b1.z; bv[7]=b1.w;
#pragma unroll
            for (int r = 0; r < 4; r++)
#pragma unroll
                for (int c = 0; c < 8; c++)
                    acc[r][c] = fmaf(av[r], bv[c], acc[r][c]);
        }
        __syncthreads();
    }

    // epilogue: write hp, compute per-row partial tanh-dots
    float* hpo = g_hp + (size_t)((b * HH + h) * NN + rb * 64) * FF;
    float sp[4], dp[4];
#pragma unroll
    for (int r = 0; r < 4; r++) {
        int row = ty * 4 + r;
        float4 o0 = make_float4(acc[r][0], acc[r][1], acc[r][2], acc[r][3]);
        float4 o1 = make_float4(acc[r][4], acc[r][5], acc[r][6], acc[r][7]);
        *(float4*)&hpo[(size_t)row * FF + tx * 8]     = o0;
        *(float4*)&hpo[(size_t)row * FF + tx * 8 + 4] = o1;
        float s = 0.0f, d = 0.0f;
#pragma unroll
        for (int c = 0; c < 8; c++) {
            float t = tanhf(acc[r][c]);
            s = fmaf(t, sa[tx * 8 + c], s);
            d = fmaf(t, da[tx * 8 + c], d);
        }
        sp[r] = s; dp[r] = d;
    }
#pragma unroll
    for (int r = 0; r < 4; r++) {
        redA[ty * 4 + r][tx] = sp[r];
        redB[ty * 4 + r][tx] = dp[r];
    }
    __syncthreads();
    if (tid < 64) {
        float s = 0.0f, d = 0.0f;
#pragma unroll
        for (int c = 0; c < 16; c++) { s += redA[tid][c]; d += redB[tid][c]; }
        int gi = (b * HH + h) * NN + rb * 64 + tid;
        g_s[gi] = s;
        g_d[gi] = d;
    }
}

// ---------------- K3: sparse attention + head-mean + bias (+ReLU) ----------
// grid B*N/4 CTAs, 128 threads (4 warps, warp per row). Lane owns 4 channels.
__global__ __launch_bounds__(128) void gat_attn(const float* __restrict__ bias,
                                                float* __restrict__ xout,
                                                int do_relu) {
    __shared__ float ps[4][MAXN];
    __shared__ int   ns[4][MAXN];
    __shared__ float bsm[FF];

    const int tid  = threadIdx.x;
    const int w    = tid >> 5;
    const int lane = tid & 31;
    bsm[tid] = bias[tid];
    __syncthreads();

    const int b = blockIdx.x / (NN / 4);
    const int i = (blockIdx.x % (NN / 4)) * 4 + w;
    const int cnt = g_cnt[b * NN + i];

    for (int k = lane; k < cnt; k += 32)
        ns[w][k] = g_nbr[(b * NN + i) * MAXN + k];
    __syncwarp();

    float ax = 0.0f, ay = 0.0f, az = 0.0f, aw = 0.0f;

    for (int h = 0; h < HH; h++) {
        const float* dv = g_d + (b * HH + h) * NN;
        const float  si = g_s[(b * HH + h) * NN + i];

        // pass 1: row max of leaky scores over neighbors
        float m = -1e30f;
        for (int k = lane; k < cnt; k += 32) {
            float sc = si + dv[ns[w][k]];
            sc = sc >= 0.0f ? sc : 0.2f * sc;
            m = fmaxf(m, sc);
        }
#pragma unroll
        for (int off = 16; off > 0; off >>= 1)
            m = fmaxf(m, __shfl_xor_sync(0xffffffffu, m, off));

        // pass 2: exp & sum
        float ssum = 0.0f;
        for (int k = lane; k < cnt; k += 32) {
            float sc = si + dv[ns[w][k]];
            sc = sc >= 0.0f ? sc : 0.2f * sc;
            float p = __expf(sc - m);
            ps[w][k] = p;
            ssum += p;
        }
#pragma unroll
        for (int off = 16; off > 0; off >>= 1)
            ssum += __shfl_xor_sync(0xffffffffu, ssum, off);
        const float wsc = (1.0f / (float)HH) / ssum;
        __syncwarp();

        // pass 3: gather-accumulate hp rows (float4 per lane, coalesced 512B)
        const float* hprow = g_hp + (size_t)(b * HH + h) * NN * FF;
        float gx = 0.0f, gy = 0.0f, gz = 0.0f, gw = 0.0f;
        for (int k = 0; k < cnt; k++) {
            float p = ps[w][k];
            int   j = ns[w][k];
            float4 v = *(const float4*)&hprow[(size_t)j * FF + lane * 4];
            gx = fmaf(p, v.x, gx);
            gy = fmaf(p, v.y, gy);
            gz = fmaf(p, v.z, gz);
            gw = fmaf(p, v.w, gw);
        }
        ax = fmaf(wsc, gx, ax);
        ay = fmaf(wsc, gy, ay);
        az = fmaf(wsc, gz, az);
        aw = fmaf(wsc, gw, aw);
        __syncwarp();  // protect ps before next head overwrites
    }

    ax += bsm[lane * 4 + 0];
    ay += bsm[lane * 4 + 1];
    az += bsm[lane * 4 + 2];
    aw += bsm[lane * 4 + 3];
    if (do_relu) {
        ax = fmaxf(ax, 0.0f); ay = fmaxf(ay, 0.0f);
        az = fmaxf(az, 0.0f); aw = fmaxf(aw, 0.0f);
    }
    *(float4*)&xout[(size_t)(b * NN + i) * FF + lane * 4] =
        make_float4(ax, ay, az, aw);
}

// ---------------- K4/K5: concat max-pool + linear --------------------------
__global__ __launch_bounds__(PRED_IN) void pool1() {
    const int chunk = blockIdx.x;   // 0..7 (128 nodes each)
    const int b     = blockIdx.y;
    const int f     = threadIdx.x;  // 0..383
    const float* src; int fo;
    if (f < 128)       { src = g_x1; fo = f; }
    else if (f < 256)  { src = g_x2; fo = f - 128; }
    else               { src = g_x3; fo = f - 256; }
    src += (size_t)b * NN * FF + fo;
    const int n0 = chunk * 128;
    float m = -INFINITY;
#pragma unroll 8
    for (int n = 0; n < 128; n++)
        m = fmaxf(m, src[(size_t)(n0 + n) * FF]);
    g_pmax[(b * 8 + chunk) * PRED_IN + f] = m;
}

__global__ __launch_bounds__(PRED_IN) void pool2(const float* __restrict__ pw,
                                                 const float* __restrict__ pb,
                                                 float* __restrict__ out) {
    __shared__ float pooled[PRED_IN];
    const int b = blockIdx.x;
    const int f = threadIdx.x;
    float m = -INFINITY;
#pragma unroll
    for (int c = 0; c < 8; c++)
        m = fmaxf(m, g_pmax[(b * 8 + c) * PRED_IN + f]);
    pooled[f] = m;
    __syncthreads();
    if (f < LDIM) {
        float acc = pb[f];
        for (int k = 0; k < PRED_IN; k++)
            acc = fmaf(pooled[k], pw[k * LDIM + f], acc);
        out[b * LDIM + f] = acc;
    }
}

// ---------------- launch ----------------------------------------------------
extern "C" void kernel_launch(void* const* d_in, const int* in_sizes, int n_in,
                              void* d_out, int out_size) {
    const float* x   = (const float*)d_in[0];
    const float* adj = (const float*)d_in[1];
    const float* w1  = (const float*)d_in[2];
    const float* as1 = (const float*)d_in[3];
    const float* ad1 = (const float*)d_in[4];
    const float* b1  = (const float*)d_in[5];
    const float* w2  = (const float*)d_in[6];
    const float* as2 = (const float*)d_in[7];
    const float* ad2 = (const float*)d_in[8];
    const float* b2  = (const float*)d_in[9];
    const float* w3  = (const float*)d_in[10];
    const float* as3 = (const float*)d_in[11];
    const float* ad3 = (const float*)d_in[12];
    const float* b3  = (const float*)d_in[13];
    const float* pw  = (const float*)d_in[14];
    const float* pb  = (const float*)d_in[15];
    float* out = (float*)d_out;

    float* x1; cudaGetSymbolAddress((void**)&x1, g_x1);
    float* x2; cudaGetSymbolAddress((void**)&x2, g_x2);
    float* x3; cudaGetSymbolAddress((void**)&x3, g_x3);

    build_nbr<<<BB * NN / 8, 256>>>(adj);

    dim3 ggrid(NN / 64, HH, BB);
    const int agrid = BB * NN / 4;

    gat_gemm<<<ggrid, 256>>>(x,  w1, as1, ad1);
    gat_attn<<<agrid, 128>>>(b1, x1, 1);

    gat_gemm<<<ggrid, 256>>>(x1, w2, as2, ad2);
    gat_attn<<<agrid, 128>>>(b2, x2, 1);

    gat_gemm<<<ggrid, 256>>>(x2, w3, as3, ad3);
    gat_attn<<<agrid, 128>>>(b3, x3, 0);

    pool1<<<dim3(8, BB), PRED_IN>>>();
    pool2<<<BB, PRED_IN>>>(pw, pb, out);
}